// round 3
// baseline (speedup 1.0000x reference)
#include <cuda_runtime.h>
#include <math.h>

#define N_ 64
#define C_ 64
#define T_ 300
#define V_ 25
#define S_ 3
#define I_ 16
#define TV_ 7500
#define KIT_ 4800
#define CT_ 19200           // C*T rows per n
#define NTV_ 480000.0       // N*T*V per channel

// ---------------- scratch (device globals; no allocation allowed) ----------------
__device__ __align__(16) float g_W[288 * 64];                  // packed [wa(48); wb(48); wd(192)] x [64]
__device__ float g_bias[288];                    // ba, bb, zeros
__device__ float g_bdsum[64];                    // sum_s bd[s][o]
__device__ __align__(16) float g_a[(size_t)N_ * 48 * TV_];     // [n][s*16+i][t*25+v]
__device__ __align__(16) float g_b[(size_t)N_ * 48 * TV_];
__device__ __align__(16) float g_xp[(size_t)N_ * 192 * TV_];   // [n][s*64+o][t*25+v]
__device__ float g_adapt[N_ * S_ * V_ * V_];     // [n][s][v][w]
__device__ __align__(16) float g_y[(size_t)N_ * C_ * TV_];     // [n][o][t][v]
__device__ float g_ps1[64 * 64];
__device__ float g_ps2[64 * 64];
__device__ float g_scale[64];
__device__ float g_shift[64];

// ---------------- K0: pack weights / biases ----------------
__global__ void k0_pack(const float* __restrict__ wa, const float* __restrict__ ba,
                        const float* __restrict__ wb, const float* __restrict__ bb,
                        const float* __restrict__ wd, const float* __restrict__ bd) {
    int idx = blockIdx.x * 256 + threadIdx.x;
    if (idx < 288 * 64) {
        int row = idx / 64, k = idx % 64;
        float v;
        if (row < 48)       v = wa[row * 64 + k];
        else if (row < 96)  v = wb[(row - 48) * 64 + k];
        else                v = wd[(row - 96) * 64 + k];
        g_W[idx] = v;
    } else if (idx < 288 * 64 + 288) {
        int row = idx - 288 * 64;
        g_bias[row] = (row < 48) ? ba[row] : ((row < 96) ? bb[row - 48] : 0.0f);
    } else if (idx < 288 * 64 + 288 + 64) {
        int o = idx - 288 * 64 - 288;
        g_bdsum[o] = bd[o] + bd[64 + o] + bd[128 + o];
    }
}

// ---------------- KG: [288,64] @ [64,7500] per n ----------------
// BM=96, BN=128, BK=32 (two phases), 192 threads, 8x8 microtile.
__global__ __launch_bounds__(192) void kg_gemm(const float* __restrict__ x) {
    __shared__ __align__(16) float As[32][96];    // [k][m]
    __shared__ __align__(16) float Bs[32][128];   // [k][col]
    const int n = blockIdx.z;
    const int rowBase = blockIdx.y * 96;
    const int col0 = blockIdx.x * 128;
    const int t = threadIdx.x;
    const int tx = t & 15;          // 0..15 (col groups of 8)
    const int ty = t >> 4;          // 0..11 (row groups of 8)
    const float* xn = x + (size_t)n * (C_ * TV_);

    float acc[8][8];
#pragma unroll
    for (int i = 0; i < 8; i++)
#pragma unroll
        for (int j = 0; j < 8; j++) acc[i][j] = 0.0f;

    for (int kb = 0; kb < 64; kb += 32) {
        // A tile: conflict-free transposed store; W is tiny & L2-resident
#pragma unroll
        for (int it = 0; it < 4; it++) {
            int idx = it * 192 + t;                  // < 768 = 96*8
            int m = idx % 96;
            int kq = idx / 96;                       // 0..7
            float4 w4 = *(const float4*)(g_W + (rowBase + m) * 64 + kb + kq * 4);
            As[kq * 4 + 0][m] = w4.x;
            As[kq * 4 + 1][m] = w4.y;
            As[kq * 4 + 2][m] = w4.z;
            As[kq * 4 + 3][m] = w4.w;
        }
        // B tile: coalesced float4 rows of x
#pragma unroll
        for (int it = 0; it < 6; it++) {
            int idx = it * 192 + t;
            if (idx < 1024) {
                int k = idx >> 5;
                int c4 = (idx & 31) * 4;
                int col = col0 + c4;
                float4 v = make_float4(0.f, 0.f, 0.f, 0.f);
                if (col + 3 < TV_)
                    v = *(const float4*)(xn + (size_t)(kb + k) * TV_ + col);
                *(float4*)(&Bs[k][c4]) = v;
            }
        }
        __syncthreads();
#pragma unroll
        for (int k = 0; k < 32; k++) {
            float a_[8], b_[8];
            *(float4*)&a_[0] = *(const float4*)&As[k][ty * 8];
            *(float4*)&a_[4] = *(const float4*)&As[k][ty * 8 + 4];
            *(float4*)&b_[0] = *(const float4*)&Bs[k][tx * 8];
            *(float4*)&b_[4] = *(const float4*)&Bs[k][tx * 8 + 4];
#pragma unroll
            for (int i = 0; i < 8; i++)
#pragma unroll
                for (int j = 0; j < 8; j++)
                    acc[i][j] = fmaf(a_[i], b_[j], acc[i][j]);
        }
        __syncthreads();
    }

    // epilogue: route rows to g_a / g_b / g_xp, add bias (ba/bb only)
#pragma unroll
    for (int im = 0; im < 8; im++) {
        int gm = rowBase + ty * 8 + im;
        float bias;
        float* dst;
        if (gm < 48)      { dst = g_a  + ((size_t)n * 48  + gm)        * TV_; bias = g_bias[gm]; }
        else if (gm < 96) { dst = g_b  + ((size_t)n * 48  + (gm - 48)) * TV_; bias = g_bias[gm]; }
        else              { dst = g_xp + ((size_t)n * 192 + (gm - 96)) * TV_; bias = 0.0f; }
        int cb = col0 + tx * 8;
        if (cb + 7 < TV_) {
            float4 r0 = make_float4(acc[im][0] + bias, acc[im][1] + bias,
                                    acc[im][2] + bias, acc[im][3] + bias);
            float4 r1 = make_float4(acc[im][4] + bias, acc[im][5] + bias,
                                    acc[im][6] + bias, acc[im][7] + bias);
            *(float4*)(dst + cb)     = r0;
            *(float4*)(dst + cb + 4) = r1;
        } else {
#pragma unroll
            for (int j = 0; j < 8; j++)
                if (cb + j < TV_) dst[cb + j] = acc[im][j] + bias;
        }
    }
}

// ---------------- K2: scores + column softmax + adapt ----------------
// block per (s, n); 640 threads; thread (v,w) = tid<625 owns one score.
__global__ __launch_bounds__(640) void k2_adapt(const float* __restrict__ Aad,
                                                const float* __restrict__ Wad) {
    __shared__ __align__(16) float ach[64][25];
    __shared__ __align__(16) float bch[64][25];
    __shared__ float ssc[25][26];
    __shared__ float smax[25];
    __shared__ float ssum[25];
    const int s = blockIdx.x;
    const int n = blockIdx.y;
    const int tid = threadIdx.x;
    const float* abase = g_a + ((size_t)n * 48 + s * 16) * TV_;
    const float* bbase = g_b + ((size_t)n * 48 + s * 16) * TV_;
    const int v = tid / 25;
    const int w = tid % 25;
    float acc = 0.0f;

    for (int c = 0; c < 75; c++) {          // 75 chunks of 64 k = 4800 = I*T
#pragma unroll
        for (int it = 0; it < 3; it++) {
            int li = it * 640 + tid;
            if (li < 1600) {
                int kk = li / 25, vv = li % 25;
                int k = c * 64 + kk;
                int i = k / 300, tt = k % 300;
                size_t off = (size_t)i * TV_ + tt * 25 + vv;
                ach[kk][vv] = abase[off];
                bch[kk][vv] = bbase[off];
            }
        }
        __syncthreads();
        if (tid < 625) {
#pragma unroll 16
            for (int kk = 0; kk < 64; kk++)
                acc = fmaf(ach[kk][v], bch[kk][w], acc);
        }
        __syncthreads();
    }

    if (tid < 625) ssc[v][w] = acc * (1.0f / (float)KIT_);
    __syncthreads();
    if (tid < 25) {
        float m = -1e30f;
        for (int vv = 0; vv < 25; vv++) m = fmaxf(m, ssc[vv][tid]);
        smax[tid] = m;
    }
    __syncthreads();
    if (tid < 625) ssc[v][w] = expf(ssc[v][w] - smax[w]);
    __syncthreads();
    if (tid < 25) {
        float sum = 0.0f;
        for (int vv = 0; vv < 25; vv++) sum += ssc[vv][tid];
        ssum[tid] = sum;
    }
    __syncthreads();
    if (tid < 625) {
        int aw = (s * 25 + v) * 25 + w;
        g_adapt[((n * 3 + s) * 25 + v) * 25 + w] = Aad[aw] + Wad[aw] + ssc[v][w] / ssum[w];
    }
}

// ---------------- K4: y[n,o,t,w] = sum_{s,v} xp * adapt + bdsum[o] ----------------
// block = 384 contiguous (o,t) rows of one n; 128 threads x 3 rows each.
__global__ __launch_bounds__(128) void k4_y() {
    __shared__ __align__(16) float ad[S_ * V_ * V_ + 1];   // 1875 (+pad -> 7504B, keeps xs 16B-aligned)
    __shared__ __align__(16) float xs[384 * 25];           // 9600 floats
    const int tid = threadIdx.x;
    const int rowBase = blockIdx.x * 384;        // 384 | 19200
    const int n = rowBase / CT_;
    const int local0 = rowBase - n * CT_;

    const float* adg = g_adapt + n * (S_ * V_ * V_);
    for (int i = tid; i < 1875; i += 128) ad[i] = adg[i];

    float acc0[25], acc1[25], acc2[25];
#pragma unroll
    for (int w = 0; w < 25; w++) { acc0[w] = 0.f; acc1[w] = 0.f; acc2[w] = 0.f; }

    for (int s = 0; s < 3; s++) {
        __syncthreads();   // ad visible (s=0); xs reads of prior s done (s>0)
        const float* src = g_xp + (size_t)n * 1440000 + (size_t)s * 480000 + (size_t)local0 * 25;
        for (int i = tid * 4; i < 9600; i += 128 * 4)
            *(float4*)&xs[i] = *(const float4*)&src[i];
        __syncthreads();
        const float* ads = ad + s * 625;
        for (int v = 0; v < 25; v++) {
            float x0 = xs[tid * 25 + v];
            float x1 = xs[(tid + 128) * 25 + v];
            float x2 = xs[(tid + 256) * 25 + v];
            const float* adv = ads + v * 25;
#pragma unroll
            for (int w = 0; w < 25; w++) {
                float a = adv[w];
                acc0[w] = fmaf(x0, a, acc0[w]);
                acc1[w] = fmaf(x1, a, acc1[w]);
                acc2[w] = fmaf(x2, a, acc2[w]);
            }
        }
    }
    __syncthreads();
    int r0g = rowBase + tid, r1g = r0g + 128, r2g = r0g + 256;
    float b0 = g_bdsum[(r0g % CT_) / 300];
    float b1 = g_bdsum[(r1g % CT_) / 300];
    float b2 = g_bdsum[(r2g % CT_) / 300];
#pragma unroll
    for (int w = 0; w < 25; w++) {
        xs[tid * 25 + w]         = acc0[w] + b0;
        xs[(tid + 128) * 25 + w] = acc1[w] + b1;
        xs[(tid + 256) * 25 + w] = acc2[w] + b2;
    }
    __syncthreads();
    float* dst = g_y + (size_t)rowBase * 25;
    for (int i = tid * 4; i < 9600; i += 128 * 4)
        *(float4*)&dst[i] = *(const float4*)&xs[i];
}

// ---------------- K5: BN stats (deterministic two-stage tree) ----------------
__global__ __launch_bounds__(256) void k5a() {
    __shared__ float r1[256], r2[256];
    const int c = blockIdx.x >> 6;
    const int n = blockIdx.x & 63;
    const int tid = threadIdx.x;
    const float* p = g_y + ((size_t)n * 64 + c) * TV_;
    float s1 = 0.f, s2 = 0.f;
    for (int i = tid; i < TV_; i += 256) { float v = p[i]; s1 += v; s2 = fmaf(v, v, s2); }
    r1[tid] = s1; r2[tid] = s2;
    __syncthreads();
    for (int off = 128; off > 0; off >>= 1) {
        if (tid < off) { r1[tid] += r1[tid + off]; r2[tid] += r2[tid + off]; }
        __syncthreads();
    }
    if (tid == 0) { g_ps1[c * 64 + n] = r1[0]; g_ps2[c * 64 + n] = r2[0]; }
}

__global__ void k5b(const float* __restrict__ gamma, const float* __restrict__ beta) {
    int c = threadIdx.x;
    if (c < 64) {
        double s1 = 0.0, s2 = 0.0;
        for (int n2 = 0; n2 < 64; n2++) { s1 += g_ps1[c * 64 + n2]; s2 += g_ps2[c * 64 + n2]; }
        double mean = s1 / NTV_;
        double var = s2 / NTV_ - mean * mean;
        float sc = gamma[c] * rsqrtf((float)var + 1e-5f);
        g_scale[c] = sc;
        g_shift[c] = beta[c] - (float)mean * sc;
    }
}

// ---------------- K6: BN apply + residual + relu ----------------
__global__ __launch_bounds__(256) void k6(const float* __restrict__ x, float* __restrict__ out) {
    size_t i = ((size_t)blockIdx.x * 256 + threadIdx.x) * 4;
    if (i >= (size_t)N_ * C_ * TV_) return;
    int c = (int)((i / TV_) & 63);
    float sc = g_scale[c], sh = g_shift[c];
    float4 yv = *(const float4*)&g_y[i];
    float4 xv = *(const float4*)&x[i];
    float4 o;
    o.x = fmaxf(fmaf(yv.x, sc, sh) + xv.x, 0.f);
    o.y = fmaxf(fmaf(yv.y, sc, sh) + xv.y, 0.f);
    o.z = fmaxf(fmaf(yv.z, sc, sh) + xv.z, 0.f);
    o.w = fmaxf(fmaf(yv.w, sc, sh) + xv.w, 0.f);
    *(float4*)&out[i] = o;
}

// ---------------- launch ----------------
extern "C" void kernel_launch(void* const* d_in, const int* in_sizes, int n_in,
                              void* d_out, int out_size) {
    const float* x     = (const float*)d_in[0];
    const float* Aad   = (const float*)d_in[1];
    const float* Wad   = (const float*)d_in[2];
    const float* wa    = (const float*)d_in[3];
    const float* ba    = (const float*)d_in[4];
    const float* wb    = (const float*)d_in[5];
    const float* bb    = (const float*)d_in[6];
    const float* wd    = (const float*)d_in[7];
    const float* bd    = (const float*)d_in[8];
    const float* gamma = (const float*)d_in[9];
    const float* beta  = (const float*)d_in[10];
    float* out = (float*)d_out;

    k0_pack<<<74, 256>>>(wa, ba, wb, bb, wd, bd);
    kg_gemm<<<dim3(59, 3, 64), 192>>>(x);
    k2_adapt<<<dim3(3, 64), 640>>>(Aad, Wad);
    k4_y<<<3200, 128>>>();
    k5a<<<4096, 256>>>();
    k5b<<<1, 64>>>(gamma, beta);
    k6<<<30000, 256>>>(x, out);
}

// round 4
// speedup vs baseline: 1.3019x; 1.3019x over previous
#include <cuda_runtime.h>
#include <math.h>

#define N_ 64
#define C_ 64
#define T_ 300
#define V_ 25
#define S_ 3
#define I_ 16
#define TV_ 7500
#define KIT_ 4800
#define CT_ 19200
#define NTV_ 480000.0

// ---------------- scratch ----------------
__device__ __align__(16) float g_W[288 * 64];
__device__ float g_bias[288];
__device__ float g_bdsum[64];
__device__ __align__(16) float g_a[(size_t)N_ * 48 * TV_];
__device__ __align__(16) float g_b[(size_t)N_ * 48 * TV_];
__device__ __align__(16) float g_xp[(size_t)N_ * 192 * TV_];
__device__ float g_adapt[N_ * S_ * V_ * V_];
__device__ __align__(16) float g_y[(size_t)N_ * C_ * TV_];
__device__ float g_ps1[64 * 64];
__device__ float g_ps2[64 * 64];
__device__ float g_scale[64];
__device__ float g_shift[64];

// ---------------- K0: pack ----------------
__global__ void k0_pack(const float* __restrict__ wa, const float* __restrict__ ba,
                        const float* __restrict__ wb, const float* __restrict__ bb,
                        const float* __restrict__ wd, const float* __restrict__ bd) {
    int idx = blockIdx.x * 256 + threadIdx.x;
    if (idx < 288 * 64) {
        int row = idx / 64, k = idx % 64;
        float v;
        if (row < 48)       v = wa[row * 64 + k];
        else if (row < 96)  v = wb[(row - 48) * 64 + k];
        else                v = wd[(row - 96) * 64 + k];
        g_W[idx] = v;
    } else if (idx < 288 * 64 + 288) {
        int row = idx - 288 * 64;
        g_bias[row] = (row < 48) ? ba[row] : ((row < 96) ? bb[row - 48] : 0.0f);
    } else if (idx < 288 * 64 + 288 + 64) {
        int o = idx - 288 * 64 - 288;
        g_bdsum[o] = bd[o] + bd[64 + o] + bd[128 + o];
    }
}

// ---------------- KG: tf32 tensor-core GEMM [288,64]@[64,7500] per n ----------------
// block tile M=96, N=128, K=64 (two BK=32 phases). 8 warps = 2(m) x 4(n),
// warp tile 48x32 = 3x4 mma(m16n8k8) tiles.
#define PM 104   // As row pad: bank = tig*8+g -> all 32 distinct
#define PN 136   // Bs row pad: bank = tig*8+g -> all 32 distinct

__device__ __forceinline__ unsigned f2tf32(float f) {
    unsigned u; asm("cvt.rna.tf32.f32 %0, %1;" : "=r"(u) : "f"(f)); return u;
}
__device__ __forceinline__ void mma8(float* d, const unsigned* a, const unsigned* b) {
    asm volatile("mma.sync.aligned.m16n8k8.row.col.f32.tf32.tf32.f32 "
        "{%0,%1,%2,%3}, {%4,%5,%6,%7}, {%8,%9}, {%0,%1,%2,%3};"
        : "+f"(d[0]), "+f"(d[1]), "+f"(d[2]), "+f"(d[3])
        : "r"(a[0]), "r"(a[1]), "r"(a[2]), "r"(a[3]), "r"(b[0]), "r"(b[1]));
}

__global__ __launch_bounds__(256) void kg_tf32(const float* __restrict__ x) {
    __shared__ __align__(16) unsigned As[32 * PM];   // [k][m] tf32 bits
    __shared__ __align__(16) unsigned Bs[32 * PN];   // [k][n] tf32 bits
    const int n = blockIdx.z;
    const int rowBase = blockIdx.y * 96;
    const int col0 = blockIdx.x * 128;
    const int t = threadIdx.x;
    const int warp = t >> 5, lane = t & 31;
    const int g = lane >> 2, tig = lane & 3;
    const int wm = warp >> 2, wn = warp & 3;
    const int mBase0 = wm * 48, nBase0 = wn * 32;
    const float* xn = x + (size_t)n * (C_ * TV_);

    float acc[3][4][4];
#pragma unroll
    for (int mt = 0; mt < 3; mt++)
#pragma unroll
        for (int nt = 0; nt < 4; nt++)
#pragma unroll
            for (int q = 0; q < 4; q++) acc[mt][nt][q] = 0.0f;

    for (int phase = 0; phase < 2; phase++) {
        const int kb0 = phase * 32;
        // A: W[rowBase+m][kb0..kb0+31] -> As[k][m]
#pragma unroll
        for (int it = 0; it < 3; it++) {
            int idx = it * 256 + t;               // < 768
            int m = idx % 96;
            int kq = idx / 96;                    // 0..7
            float4 w4 = *(const float4*)(g_W + (rowBase + m) * 64 + kb0 + kq * 4);
            As[(kq * 4 + 0) * PM + m] = f2tf32(w4.x);
            As[(kq * 4 + 1) * PM + m] = f2tf32(w4.y);
            As[(kq * 4 + 2) * PM + m] = f2tf32(w4.z);
            As[(kq * 4 + 3) * PM + m] = f2tf32(w4.w);
        }
        // B: x[kb0+k][col0..col0+127] -> Bs[k][c]
#pragma unroll
        for (int it = 0; it < 4; it++) {
            int idx = it * 256 + t;               // < 1024
            int k = idx >> 5;
            int c4 = (idx & 31) * 4;
            int col = col0 + c4;
            float4 v = make_float4(0.f, 0.f, 0.f, 0.f);
            if (col + 3 < TV_)
                v = *(const float4*)(xn + (size_t)(kb0 + k) * TV_ + col);
            unsigned* dst = &Bs[k * PN + c4];
            dst[0] = f2tf32(v.x); dst[1] = f2tf32(v.y);
            dst[2] = f2tf32(v.z); dst[3] = f2tf32(v.w);
        }
        __syncthreads();
#pragma unroll
        for (int ks = 0; ks < 4; ks++) {
            const int kb = ks * 8;
            unsigned a[3][4], b[4][2];
#pragma unroll
            for (int mt = 0; mt < 3; mt++) {
                int mB = mBase0 + mt * 16;
                a[mt][0] = As[(kb + tig) * PM + mB + g];
                a[mt][1] = As[(kb + tig) * PM + mB + g + 8];
                a[mt][2] = As[(kb + tig + 4) * PM + mB + g];
                a[mt][3] = As[(kb + tig + 4) * PM + mB + g + 8];
            }
#pragma unroll
            for (int nt = 0; nt < 4; nt++) {
                int nB = nBase0 + nt * 8;
                b[nt][0] = Bs[(kb + tig) * PN + nB + g];
                b[nt][1] = Bs[(kb + tig + 4) * PN + nB + g];
            }
#pragma unroll
            for (int mt = 0; mt < 3; mt++)
#pragma unroll
                for (int nt = 0; nt < 4; nt++)
                    mma8(acc[mt][nt], a[mt], b[nt]);
        }
        __syncthreads();
    }

    // epilogue: D row g -> (c0,c1), row g+8 -> (c2,c3)
#pragma unroll
    for (int mt = 0; mt < 3; mt++) {
#pragma unroll
        for (int h = 0; h < 2; h++) {
            int gm = rowBase + mBase0 + mt * 16 + g + h * 8;
            float bias; float* dst;
            if (gm < 48)      { dst = g_a  + ((size_t)n * 48  + gm)        * TV_; bias = g_bias[gm]; }
            else if (gm < 96) { dst = g_b  + ((size_t)n * 48  + (gm - 48)) * TV_; bias = g_bias[gm]; }
            else              { dst = g_xp + ((size_t)n * 192 + (gm - 96)) * TV_; bias = 0.0f; }
#pragma unroll
            for (int nt = 0; nt < 4; nt++) {
                int col = col0 + nBase0 + nt * 8 + tig * 2;
                if (col < TV_) {
                    float2 v = make_float2(acc[mt][nt][h * 2 + 0] + bias,
                                           acc[mt][nt][h * 2 + 1] + bias);
                    *(float2*)(dst + col) = v;
                }
            }
        }
    }
}

// ---------------- K2: scores + column softmax + adapt ----------------
__global__ __launch_bounds__(640) void k2_adapt(const float* __restrict__ Aad,
                                                const float* __restrict__ Wad) {
    __shared__ __align__(16) float ach[64][25];
    __shared__ __align__(16) float bch[64][25];
    __shared__ float ssc[25][26];
    __shared__ float smax[25];
    __shared__ float ssum[25];
    const int s = blockIdx.x;
    const int n = blockIdx.y;
    const int tid = threadIdx.x;
    const float* abase = g_a + ((size_t)n * 48 + s * 16) * TV_;
    const float* bbase = g_b + ((size_t)n * 48 + s * 16) * TV_;
    const int v = tid / 25;
    const int w = tid % 25;
    float acc = 0.0f;

    for (int c = 0; c < 75; c++) {
#pragma unroll
        for (int it = 0; it < 3; it++) {
            int li = it * 640 + tid;
            if (li < 1600) {
                int kk = li / 25, vv = li % 25;
                int k = c * 64 + kk;
                int i = k / 300, tt = k % 300;
                size_t off = (size_t)i * TV_ + tt * 25 + vv;
                ach[kk][vv] = abase[off];
                bch[kk][vv] = bbase[off];
            }
        }
        __syncthreads();
        if (tid < 625) {
#pragma unroll 16
            for (int kk = 0; kk < 64; kk++)
                acc = fmaf(ach[kk][v], bch[kk][w], acc);
        }
        __syncthreads();
    }

    if (tid < 625) ssc[v][w] = acc * (1.0f / (float)KIT_);
    __syncthreads();
    if (tid < 25) {
        float m = -1e30f;
        for (int vv = 0; vv < 25; vv++) m = fmaxf(m, ssc[vv][tid]);
        smax[tid] = m;
    }
    __syncthreads();
    if (tid < 625) ssc[v][w] = expf(ssc[v][w] - smax[w]);
    __syncthreads();
    if (tid < 25) {
        float sum = 0.0f;
        for (int vv = 0; vv < 25; vv++) sum += ssc[vv][tid];
        ssum[tid] = sum;
    }
    __syncthreads();
    if (tid < 625) {
        int aw = (s * 25 + v) * 25 + w;
        g_adapt[((n * 3 + s) * 25 + v) * 25 + w] = Aad[aw] + Wad[aw] + ssc[v][w] / ssum[w];
    }
}

// ---------------- K4: adapt contraction; adv rows padded to 28 + float4 loads ----------------
__global__ __launch_bounds__(128, 4) void k4_y() {
    __shared__ __align__(16) float ad[3 * 25 * 28];        // 2100 floats = 8400B
    __shared__ __align__(16) float xs[384 * 25];           // 38400B
    const int tid = threadIdx.x;
    const int rowBase = blockIdx.x * 384;
    const int n = rowBase / CT_;
    const int local0 = rowBase - n * CT_;

    const float* adg = g_adapt + n * (S_ * V_ * V_);
    for (int i = tid; i < 2100; i += 128) {
        int vv = i / 28, w = i % 28;                        // vv = s*25+v
        ad[i] = (w < 25) ? adg[vv * 25 + w] : 0.0f;
    }

    float acc0[25], acc1[25], acc2[25];
#pragma unroll
    for (int w = 0; w < 25; w++) { acc0[w] = 0.f; acc1[w] = 0.f; acc2[w] = 0.f; }

    for (int s = 0; s < 3; s++) {
        __syncthreads();
        const float* src = g_xp + (size_t)n * 1440000 + (size_t)s * 480000 + (size_t)local0 * 25;
        for (int i = tid * 4; i < 9600; i += 128 * 4)
            *(float4*)&xs[i] = *(const float4*)&src[i];
        __syncthreads();
        const float* ads = ad + s * 700;
        for (int v = 0; v < 25; v++) {
            float x0 = xs[tid * 25 + v];
            float x1 = xs[(tid + 128) * 25 + v];
            float x2 = xs[(tid + 256) * 25 + v];
            float a_[28];
#pragma unroll
            for (int q = 0; q < 7; q++)
                *(float4*)&a_[q * 4] = *(const float4*)&ads[v * 28 + q * 4];
#pragma unroll
            for (int w = 0; w < 25; w++) {
                acc0[w] = fmaf(x0, a_[w], acc0[w]);
                acc1[w] = fmaf(x1, a_[w], acc1[w]);
                acc2[w] = fmaf(x2, a_[w], acc2[w]);
            }
        }
    }
    __syncthreads();
    int r0g = rowBase + tid, r1g = r0g + 128, r2g = r0g + 256;
    float b0 = g_bdsum[(r0g % CT_) / 300];
    float b1 = g_bdsum[(r1g % CT_) / 300];
    float b2 = g_bdsum[(r2g % CT_) / 300];
#pragma unroll
    for (int w = 0; w < 25; w++) {
        xs[tid * 25 + w]         = acc0[w] + b0;
        xs[(tid + 128) * 25 + w] = acc1[w] + b1;
        xs[(tid + 256) * 25 + w] = acc2[w] + b2;
    }
    __syncthreads();
    float* dst = g_y + (size_t)rowBase * 25;
    for (int i = tid * 4; i < 9600; i += 128 * 4)
        *(float4*)&dst[i] = *(const float4*)&xs[i];
}

// ---------------- K5: BN stats ----------------
__global__ __launch_bounds__(256) void k5a() {
    __shared__ float r1[256], r2[256];
    const int c = blockIdx.x >> 6;
    const int n = blockIdx.x & 63;
    const int tid = threadIdx.x;
    const float* p = g_y + ((size_t)n * 64 + c) * TV_;
    float s1 = 0.f, s2 = 0.f;
    for (int i = tid; i < TV_; i += 256) { float v = p[i]; s1 += v; s2 = fmaf(v, v, s2); }
    r1[tid] = s1; r2[tid] = s2;
    __syncthreads();
    for (int off = 128; off > 0; off >>= 1) {
        if (tid < off) { r1[tid] += r1[tid + off]; r2[tid] += r2[tid + off]; }
        __syncthreads();
    }
    if (tid == 0) { g_ps1[c * 64 + n] = r1[0]; g_ps2[c * 64 + n] = r2[0]; }
}

__global__ void k5b(const float* __restrict__ gamma, const float* __restrict__ beta) {
    int c = threadIdx.x;
    if (c < 64) {
        double s1 = 0.0, s2 = 0.0;
        for (int n2 = 0; n2 < 64; n2++) { s1 += g_ps1[c * 64 + n2]; s2 += g_ps2[c * 64 + n2]; }
        double mean = s1 / NTV_;
        double var = s2 / NTV_ - mean * mean;
        float sc = gamma[c] * rsqrtf((float)var + 1e-5f);
        g_scale[c] = sc;
        g_shift[c] = beta[c] - (float)mean * sc;
    }
}

// ---------------- K6: BN apply + residual + relu ----------------
__global__ __launch_bounds__(256) void k6(const float* __restrict__ x, float* __restrict__ out) {
    size_t i = ((size_t)blockIdx.x * 256 + threadIdx.x) * 4;
    if (i >= (size_t)N_ * C_ * TV_) return;
    int c = (int)((i / TV_) & 63);
    float sc = g_scale[c], sh = g_shift[c];
    float4 yv = *(const float4*)&g_y[i];
    float4 xv = *(const float4*)&x[i];
    float4 o;
    o.x = fmaxf(fmaf(yv.x, sc, sh) + xv.x, 0.f);
    o.y = fmaxf(fmaf(yv.y, sc, sh) + xv.y, 0.f);
    o.z = fmaxf(fmaf(yv.z, sc, sh) + xv.z, 0.f);
    o.w = fmaxf(fmaf(yv.w, sc, sh) + xv.w, 0.f);
    *(float4*)&out[i] = o;
}

// ---------------- launch ----------------
extern "C" void kernel_launch(void* const* d_in, const int* in_sizes, int n_in,
                              void* d_out, int out_size) {
    const float* x     = (const float*)d_in[0];
    const float* Aad   = (const float*)d_in[1];
    const float* Wad   = (const float*)d_in[2];
    const float* wa    = (const float*)d_in[3];
    const float* ba    = (const float*)d_in[4];
    const float* wb    = (const float*)d_in[5];
    const float* bb    = (const float*)d_in[6];
    const float* wd    = (const float*)d_in[7];
    const float* bd    = (const float*)d_in[8];
    const float* gamma = (const float*)d_in[9];
    const float* beta  = (const float*)d_in[10];
    float* out = (float*)d_out;

    k0_pack<<<74, 256>>>(wa, ba, wb, bb, wd, bd);
    kg_tf32<<<dim3(59, 3, 64), 256>>>(x);
    k2_adapt<<<dim3(3, 64), 640>>>(Aad, Wad);
    k4_y<<<3200, 128>>>();
    k5a<<<4096, 256>>>();
    k5b<<<1, 64>>>(gamma, beta);
    k6<<<30000, 256>>>(x, out);
}

// round 6
// speedup vs baseline: 1.3334x; 1.0242x over previous
#include <cuda_runtime.h>
#include <math.h>

#define N_ 64
#define C_ 64
#define T_ 300
#define V_ 25
#define S_ 3
#define I_ 16
#define TV_ 7500
#define KIT_ 4800
#define CT_ 19200
#define NTV_ 480000.0

// ---------------- scratch ----------------
__device__ __align__(16) float g_W[288 * 64];
__device__ float g_bias[288];
__device__ float g_bdsum[64];
__device__ __align__(16) float g_a[(size_t)N_ * 48 * TV_];
__device__ __align__(16) float g_b[(size_t)N_ * 48 * TV_];
__device__ __align__(16) float g_xp[(size_t)N_ * 192 * TV_];
__device__ float g_adapt[N_ * S_ * V_ * V_];
__device__ __align__(16) float g_y[(size_t)N_ * C_ * TV_];
__device__ float g_pb[4800 * 4];        // per-block BN partials {s1_lo,s2_lo,s1_hi,s2_hi}
__device__ float g_scale[64];
__device__ float g_shift[64];

__device__ __forceinline__ unsigned f2tf32(float f) {
    unsigned u; asm("cvt.rna.tf32.f32 %0, %1;" : "=r"(u) : "f"(f)); return u;
}
__device__ __forceinline__ void mma8(float* d, const unsigned* a, const unsigned* b) {
    asm volatile("mma.sync.aligned.m16n8k8.row.col.f32.tf32.tf32.f32 "
        "{%0,%1,%2,%3}, {%4,%5,%6,%7}, {%8,%9}, {%0,%1,%2,%3};"
        : "+f"(d[0]), "+f"(d[1]), "+f"(d[2]), "+f"(d[3])
        : "r"(a[0]), "r"(a[1]), "r"(a[2]), "r"(a[3]), "r"(b[0]), "r"(b[1]));
}

// ---------------- K0: pack ----------------
__global__ void k0_pack(const float* __restrict__ wa, const float* __restrict__ ba,
                        const float* __restrict__ wb, const float* __restrict__ bb,
                        const float* __restrict__ wd, const float* __restrict__ bd) {
    int idx = blockIdx.x * 256 + threadIdx.x;
    if (idx < 288 * 64) {
        int row = idx / 64, k = idx % 64;
        float v;
        if (row < 48)       v = wa[row * 64 + k];
        else if (row < 96)  v = wb[(row - 48) * 64 + k];
        else                v = wd[(row - 96) * 64 + k];
        g_W[idx] = v;
    } else if (idx < 288 * 64 + 288) {
        int row = idx - 288 * 64;
        g_bias[row] = (row < 48) ? ba[row] : ((row < 96) ? bb[row - 48] : 0.0f);
    } else if (idx < 288 * 64 + 288 + 64) {
        int o = idx - 288 * 64 - 288;
        g_bdsum[o] = bd[o] + bd[64 + o] + bd[128 + o];
    }
}

// ---------------- KG: tf32 GEMM [288,64]@[64,7500] per n (R4-validated) ----------------
#define PM 104
#define PN 136

__global__ __launch_bounds__(256) void kg_tf32(const float* __restrict__ x) {
    __shared__ __align__(16) unsigned As[32 * PM];
    __shared__ __align__(16) unsigned Bs[32 * PN];
    const int n = blockIdx.z;
    const int rowBase = blockIdx.x * 96;
    const int col0 = blockIdx.y * 128;
    const int t = threadIdx.x;
    const int warp = t >> 5, lane = t & 31;
    const int g = lane >> 2, tig = lane & 3;
    const int wm = warp >> 2, wn = warp & 3;
    const int mBase0 = wm * 48, nBase0 = wn * 32;
    const float* xn = x + (size_t)n * (C_ * TV_);

    float acc[3][4][4];
#pragma unroll
    for (int mt = 0; mt < 3; mt++)
#pragma unroll
        for (int nt = 0; nt < 4; nt++)
#pragma unroll
            for (int q = 0; q < 4; q++) acc[mt][nt][q] = 0.0f;

    for (int phase = 0; phase < 2; phase++) {
        const int kb0 = phase * 32;
#pragma unroll
        for (int it = 0; it < 3; it++) {
            int idx = it * 256 + t;
            int m = idx % 96;
            int kq = idx / 96;
            float4 w4 = *(const float4*)(g_W + (rowBase + m) * 64 + kb0 + kq * 4);
            As[(kq * 4 + 0) * PM + m] = f2tf32(w4.x);
            As[(kq * 4 + 1) * PM + m] = f2tf32(w4.y);
            As[(kq * 4 + 2) * PM + m] = f2tf32(w4.z);
            As[(kq * 4 + 3) * PM + m] = f2tf32(w4.w);
        }
#pragma unroll
        for (int it = 0; it < 4; it++) {
            int idx = it * 256 + t;
            int k = idx >> 5;
            int c4 = (idx & 31) * 4;
            int col = col0 + c4;
            float4 v = make_float4(0.f, 0.f, 0.f, 0.f);
            if (col + 3 < TV_)
                v = *(const float4*)(xn + (size_t)(kb0 + k) * TV_ + col);
            unsigned* dst = &Bs[k * PN + c4];
            dst[0] = f2tf32(v.x); dst[1] = f2tf32(v.y);
            dst[2] = f2tf32(v.z); dst[3] = f2tf32(v.w);
        }
        __syncthreads();
#pragma unroll
        for (int ks = 0; ks < 4; ks++) {
            const int kb = ks * 8;
            unsigned a[3][4], b[4][2];
#pragma unroll
            for (int mt = 0; mt < 3; mt++) {
                int mB = mBase0 + mt * 16;
                a[mt][0] = As[(kb + tig) * PM + mB + g];
                a[mt][1] = As[(kb + tig) * PM + mB + g + 8];
                a[mt][2] = As[(kb + tig + 4) * PM + mB + g];
                a[mt][3] = As[(kb + tig + 4) * PM + mB + g + 8];
            }
#pragma unroll
            for (int nt = 0; nt < 4; nt++) {
                int nB = nBase0 + nt * 8;
                b[nt][0] = Bs[(kb + tig) * PN + nB + g];
                b[nt][1] = Bs[(kb + tig + 4) * PN + nB + g];
            }
#pragma unroll
            for (int mt = 0; mt < 3; mt++)
#pragma unroll
                for (int nt = 0; nt < 4; nt++)
                    mma8(acc[mt][nt], a[mt], b[nt]);
        }
        __syncthreads();
    }

#pragma unroll
    for (int mt = 0; mt < 3; mt++) {
#pragma unroll
        for (int h = 0; h < 2; h++) {
            int gm = rowBase + mBase0 + mt * 16 + g + h * 8;
            float bias; float* dst;
            if (gm < 48)      { dst = g_a  + ((size_t)n * 48  + gm)        * TV_; bias = g_bias[gm]; }
            else if (gm < 96) { dst = g_b  + ((size_t)n * 48  + (gm - 48)) * TV_; bias = g_bias[gm]; }
            else              { dst = g_xp + ((size_t)n * 192 + (gm - 96)) * TV_; bias = 0.0f; }
#pragma unroll
            for (int nt = 0; nt < 4; nt++) {
                int col = col0 + nBase0 + nt * 8 + tig * 2;
                if (col < TV_) {
                    float2 v = make_float2(acc[mt][nt][h * 2 + 0] + bias,
                                           acc[mt][nt][h * 2 + 1] + bias);
                    *(float2*)(dst + col) = v;
                }
            }
        }
    }
}

// ---------------- K2: scalar scores + softmax + adapt (R4-validated, verbatim) ----------------
__global__ __launch_bounds__(640) void k2_adapt(const float* __restrict__ Aad,
                                                const float* __restrict__ Wad) {
    __shared__ __align__(16) float ach[64][25];
    __shared__ __align__(16) float bch[64][25];
    __shared__ float ssc[25][26];
    __shared__ float smax[25];
    __shared__ float ssum[25];
    const int s = blockIdx.x;
    const int n = blockIdx.y;
    const int tid = threadIdx.x;
    const float* abase = g_a + ((size_t)n * 48 + s * 16) * TV_;
    const float* bbase = g_b + ((size_t)n * 48 + s * 16) * TV_;
    const int v = tid / 25;
    const int w = tid % 25;
    float acc = 0.0f;

    for (int c = 0; c < 75; c++) {
#pragma unroll
        for (int it = 0; it < 3; it++) {
            int li = it * 640 + tid;
            if (li < 1600) {
                int kk = li / 25, vv = li % 25;
                int k = c * 64 + kk;
                int i = k / 300, tt = k % 300;
                size_t off = (size_t)i * TV_ + tt * 25 + vv;
                ach[kk][vv] = abase[off];
                bch[kk][vv] = bbase[off];
            }
        }
        __syncthreads();
        if (tid < 625) {
#pragma unroll 16
            for (int kk = 0; kk < 64; kk++)
                acc = fmaf(ach[kk][v], bch[kk][w], acc);
        }
        __syncthreads();
    }

    if (tid < 625) ssc[v][w] = acc * (1.0f / (float)KIT_);
    __syncthreads();
    if (tid < 25) {
        float m = -1e30f;
        for (int vv = 0; vv < 25; vv++) m = fmaxf(m, ssc[vv][tid]);
        smax[tid] = m;
    }
    __syncthreads();
    if (tid < 625) ssc[v][w] = expf(ssc[v][w] - smax[w]);
    __syncthreads();
    if (tid < 25) {
        float sum = 0.0f;
        for (int vv = 0; vv < 25; vv++) sum += ssc[vv][tid];
        ssum[tid] = sum;
    }
    __syncthreads();
    if (tid < 625) {
        int aw = (s * 25 + v) * 25 + w;
        g_adapt[((n * 3 + s) * 25 + v) * 25 + w] = Aad[aw] + Wad[aw] + ssc[v][w] / ssum[w];
    }
}

// ---------------- K4: tf32 MMA y = sum_s xp_s @ adapt_s + bd, fused BN partials ----------------
#define XP 36
__global__ __launch_bounds__(256) void k4_mma() {
    __shared__ __align__(16) unsigned xs[256 * XP];   // 36864B; reused as float y staging
    __shared__ __align__(16) unsigned ads[32 * 40];   // 5120B
    __shared__ float rb[256 * 4];                     // 4096B BN reduce
    const int bi = blockIdx.x;
    const int n = bi / 75;
    const int local0 = (bi % 75) * 256;
    const int tid = threadIdx.x, warp = tid >> 5, lane = tid & 31;
    const int g = lane >> 2, tig = lane & 3;
    const int mB0 = warp * 32;

    float acc[2][4][4];
#pragma unroll
    for (int mt = 0; mt < 2; mt++)
#pragma unroll
        for (int nt = 0; nt < 4; nt++)
#pragma unroll
            for (int q = 0; q < 4; q++) acc[mt][nt][q] = 0.0f;

    // zero xs pad columns (cols 25..35) once
    {
        int r = tid;
#pragma unroll
        for (int cpd = 25; cpd < XP; cpd++) xs[r * XP + cpd] = 0u;
    }
    const float* adg = g_adapt + n * (S_ * V_ * V_);

    for (int s = 0; s < 3; s++) {
        __syncthreads();
        for (int i = tid; i < 1280; i += 256) {
            int v = i / 40, w = i % 40;
            float val = (v < 25 && w < 25) ? adg[(s * 25 + v) * 25 + w] : 0.0f;
            ads[i] = f2tf32(val);
        }
        const float* src = g_xp + (size_t)n * 1440000 + (size_t)s * 480000 + (size_t)local0 * 25;
        for (int i = tid; i < 6400; i += 256) {
            int r = i / 25, v = i % 25;
            xs[r * XP + v] = f2tf32(src[i]);
        }
        __syncthreads();
#pragma unroll
        for (int ks = 0; ks < 4; ks++) {
            const int kb = ks * 8;
            unsigned af[2][4], bf[4][2];
#pragma unroll
            for (int mt = 0; mt < 2; mt++) {
                int mB = mB0 + mt * 16;
                af[mt][0] = xs[(mB + g) * XP + kb + tig];
                af[mt][1] = xs[(mB + g + 8) * XP + kb + tig];
                af[mt][2] = xs[(mB + g) * XP + kb + tig + 4];
                af[mt][3] = xs[(mB + g + 8) * XP + kb + tig + 4];
            }
#pragma unroll
            for (int nt = 0; nt < 4; nt++) {
                bf[nt][0] = ads[(kb + tig) * 40 + nt * 8 + g];
                bf[nt][1] = ads[(kb + tig + 4) * 40 + nt * 8 + g];
            }
#pragma unroll
            for (int mt = 0; mt < 2; mt++)
#pragma unroll
                for (int nt = 0; nt < 4; nt++)
                    mma8(acc[mt][nt], af[mt], bf[nt]);
        }
    }
    __syncthreads();

    // stage y (with bias) into xs as float
    float* ys = (float*)xs;
#pragma unroll
    for (int mt = 0; mt < 2; mt++) {
#pragma unroll
        for (int h = 0; h < 2; h++) {
            int row = mB0 + mt * 16 + g + h * 8;
            float bias = g_bdsum[(local0 + row) / 300];
#pragma unroll
            for (int nt = 0; nt < 4; nt++) {
#pragma unroll
                for (int e = 0; e < 2; e++) {
                    int col = nt * 8 + tig * 2 + e;
                    if (col < 25) ys[row * 25 + col] = acc[mt][nt][h * 2 + e] + bias;
                }
            }
        }
    }
    __syncthreads();

    // BN partials over the two channels this block spans
    const int o_lo = local0 / 300;
    int split = (o_lo + 1) * 300 - local0;
    if (split > 256) split = 256;
    const int splitf = split * 25;
    float s10 = 0.f, s20 = 0.f, s11 = 0.f, s21 = 0.f;
    for (int i = tid; i < 6400; i += 256) {
        float v = ys[i];
        if (i < splitf) { s10 += v; s20 = fmaf(v, v, s20); }
        else            { s11 += v; s21 = fmaf(v, v, s21); }
    }
    rb[tid * 4 + 0] = s10; rb[tid * 4 + 1] = s20;
    rb[tid * 4 + 2] = s11; rb[tid * 4 + 3] = s21;
    __syncthreads();
    for (int off = 128; off > 0; off >>= 1) {
        if (tid < off) {
#pragma unroll
            for (int j = 0; j < 4; j++)
                rb[tid * 4 + j] += rb[(tid + off) * 4 + j];
        }
        __syncthreads();
    }
    if (tid < 4) g_pb[bi * 4 + tid] = rb[tid];

    // write y tile (contiguous 6400 floats)
    float* dst = g_y + (size_t)n * 480000 + (size_t)local0 * 25;
    for (int i = tid * 4; i < 6400; i += 1024)
        *(float4*)&dst[i] = *(float4*)&ys[i];
}

// ---------------- K5b: reduce block partials -> scale/shift ----------------
__global__ __launch_bounds__(256) void k5b(const float* __restrict__ gamma,
                                           const float* __restrict__ beta) {
    __shared__ float r1[256], r2[256];
    const int c = blockIdx.x;
    const int tid = threadIdx.x;
    float s1 = 0.f, s2 = 0.f;
    for (int bi = tid; bi < 4800; bi += 256) {
        int lb = bi % 75;
        int l0 = lb * 256;
        int olo = l0 / 300;
        int ohi = (l0 + 255) / 300;
        const float* pb = g_pb + bi * 4;
        if (olo == c) { s1 += pb[0]; s2 += pb[1]; }
        if (ohi == c && ohi != olo) { s1 += pb[2]; s2 += pb[3]; }
    }
    r1[tid] = s1; r2[tid] = s2;
    __syncthreads();
    for (int off = 128; off > 0; off >>= 1) {
        if (tid < off) { r1[tid] += r1[tid + off]; r2[tid] += r2[tid + off]; }
        __syncthreads();
    }
    if (tid == 0) {
        double mean = (double)r1[0] / NTV_;
        double var = (double)r2[0] / NTV_ - mean * mean;
        float sc = gamma[c] * rsqrtf((float)var + 1e-5f);
        g_scale[c] = sc;
        g_shift[c] = beta[c] - (float)mean * sc;
    }
}

// ---------------- K6: BN apply + residual + relu ----------------
__global__ __launch_bounds__(256) void k6(const float* __restrict__ x, float* __restrict__ out) {
    size_t i = ((size_t)blockIdx.x * 256 + threadIdx.x) * 4;
    if (i >= (size_t)N_ * C_ * TV_) return;
    int c = (int)((i / TV_) & 63);
    float sc = g_scale[c], sh = g_shift[c];
    float4 yv = *(const float4*)&g_y[i];
    float4 xv = *(const float4*)&x[i];
    float4 o;
    o.x = fmaxf(fmaf(yv.x, sc, sh) + xv.x, 0.f);
    o.y = fmaxf(fmaf(yv.y, sc, sh) + xv.y, 0.f);
    o.z = fmaxf(fmaf(yv.z, sc, sh) + xv.z, 0.f);
    o.w = fmaxf(fmaf(yv.w, sc, sh) + xv.w, 0.f);
    *(float4*)&out[i] = o;
}

// ---------------- launch ----------------
extern "C" void kernel_launch(void* const* d_in, const int* in_sizes, int n_in,
                              void* d_out, int out_size) {
    const float* x     = (const float*)d_in[0];
    const float* Aad   = (const float*)d_in[1];
    const float* Wad   = (const float*)d_in[2];
    const float* wa    = (const float*)d_in[3];
    const float* ba    = (const float*)d_in[4];
    const float* wb    = (const float*)d_in[5];
    const float* bb    = (const float*)d_in[6];
    const float* wd    = (const float*)d_in[7];
    const float* bd    = (const float*)d_in[8];
    const float* gamma = (const float*)d_in[9];
    const float* beta  = (const float*)d_in[10];
    float* out = (float*)d_out;

    k0_pack<<<74, 256>>>(wa, ba, wb, bb, wd, bd);
    kg_tf32<<<dim3(3, 59, 64), 256>>>(x);
    k2_adapt<<<dim3(3, 64), 640>>>(Aad, Wad);
    k4_mma<<<4800, 256>>>();
    k5b<<<64, 256>>>(gamma, beta);
    k6<<<30000, 256>>>(x, out);
}

// round 7
// speedup vs baseline: 1.7556x; 1.3167x over previous
#include <cuda_runtime.h>
#include <math.h>

#define N_ 64
#define C_ 64
#define T_ 300
#define V_ 25
#define S_ 3
#define I_ 16
#define TV_ 7500
#define KIT_ 4800
#define CT_ 19200
#define NTV_ 480000.0

// ---------------- scratch ----------------
__device__ __align__(16) unsigned g_Wt[288 * 64];                 // packed weights, tf32 bits
__device__ float g_bias[288];
__device__ float g_bdsum[64];
__device__ __align__(16) float g_a[(size_t)N_ * 48 * TV_];
__device__ __align__(16) float g_b[(size_t)N_ * 48 * TV_];
__device__ __align__(16) unsigned g_xpu[(size_t)N_ * 192 * TV_];  // xp as tf32 bits
__device__ float g_psc[3 * 64 * 5 * 676];                         // k2 partial scores [s][n][q][26*26]
__device__ float g_adapt[N_ * S_ * V_ * V_];
__device__ __align__(16) float g_y[(size_t)N_ * C_ * TV_];
__device__ float g_pb[4800 * 4];
__device__ float g_scale[64];
__device__ float g_shift[64];

__device__ __forceinline__ unsigned f2tf32(float f) {
    unsigned u; asm("cvt.rna.tf32.f32 %0, %1;" : "=r"(u) : "f"(f)); return u;
}
__device__ __forceinline__ void mma8(float* d, const unsigned* a, const unsigned* b) {
    asm volatile("mma.sync.aligned.m16n8k8.row.col.f32.tf32.tf32.f32 "
        "{%0,%1,%2,%3}, {%4,%5,%6,%7}, {%8,%9}, {%0,%1,%2,%3};"
        : "+f"(d[0]), "+f"(d[1]), "+f"(d[2]), "+f"(d[3])
        : "r"(a[0]), "r"(a[1]), "r"(a[2]), "r"(a[3]), "r"(b[0]), "r"(b[1]));
}

// ---------------- K0: pack (weights pre-converted to tf32 bits) ----------------
__global__ void k0_pack(const float* __restrict__ wa, const float* __restrict__ ba,
                        const float* __restrict__ wb, const float* __restrict__ bb,
                        const float* __restrict__ wd, const float* __restrict__ bd) {
    int idx = blockIdx.x * 256 + threadIdx.x;
    if (idx < 288 * 64) {
        int row = idx / 64, k = idx % 64;
        float v;
        if (row < 48)       v = wa[row * 64 + k];
        else if (row < 96)  v = wb[(row - 48) * 64 + k];
        else                v = wd[(row - 96) * 64 + k];
        g_Wt[idx] = f2tf32(v);
    } else if (idx < 288 * 64 + 288) {
        int row = idx - 288 * 64;
        g_bias[row] = (row < 48) ? ba[row] : ((row < 96) ? bb[row - 48] : 0.0f);
    } else if (idx < 288 * 64 + 288 + 64) {
        int o = idx - 288 * 64 - 288;
        g_bdsum[o] = bd[o] + bd[64 + o] + bd[128 + o];
    }
}

// ---------------- KG: tf32 GEMM [288,64]@[64,7500] per n ----------------
#define PM 104
#define PN 136

__global__ __launch_bounds__(256) void kg_tf32(const float* __restrict__ x) {
    __shared__ __align__(16) unsigned As[32 * PM];
    __shared__ __align__(16) unsigned Bs[32 * PN];
    const int n = blockIdx.z;
    const int rowBase = blockIdx.x * 96;
    const int col0 = blockIdx.y * 128;
    const int t = threadIdx.x;
    const int warp = t >> 5, lane = t & 31;
    const int g = lane >> 2, tig = lane & 3;
    const int wm = warp >> 2, wn = warp & 3;
    const int mBase0 = wm * 48, nBase0 = wn * 32;
    const float* xn = x + (size_t)n * (C_ * TV_);

    float acc[3][4][4];
#pragma unroll
    for (int mt = 0; mt < 3; mt++)
#pragma unroll
        for (int nt = 0; nt < 4; nt++)
#pragma unroll
            for (int q = 0; q < 4; q++) acc[mt][nt][q] = 0.0f;

    for (int phase = 0; phase < 2; phase++) {
        const int kb0 = phase * 32;
#pragma unroll
        for (int it = 0; it < 3; it++) {
            int idx = it * 256 + t;
            int m = idx % 96;
            int kq = idx / 96;
            uint4 w4 = *(const uint4*)(g_Wt + (rowBase + m) * 64 + kb0 + kq * 4);
            As[(kq * 4 + 0) * PM + m] = w4.x;
            As[(kq * 4 + 1) * PM + m] = w4.y;
            As[(kq * 4 + 2) * PM + m] = w4.z;
            As[(kq * 4 + 3) * PM + m] = w4.w;
        }
#pragma unroll
        for (int it = 0; it < 4; it++) {
            int idx = it * 256 + t;
            int k = idx >> 5;
            int c4 = (idx & 31) * 4;
            int col = col0 + c4;
            float4 v = make_float4(0.f, 0.f, 0.f, 0.f);
            if (col + 3 < TV_)
                v = *(const float4*)(xn + (size_t)(kb0 + k) * TV_ + col);
            unsigned* dst = &Bs[k * PN + c4];
            dst[0] = f2tf32(v.x); dst[1] = f2tf32(v.y);
            dst[2] = f2tf32(v.z); dst[3] = f2tf32(v.w);
        }
        __syncthreads();
#pragma unroll
        for (int ks = 0; ks < 4; ks++) {
            const int kb = ks * 8;
            unsigned a[3][4], b[4][2];
#pragma unroll
            for (int mt = 0; mt < 3; mt++) {
                int mB = mBase0 + mt * 16;
                a[mt][0] = As[(kb + tig) * PM + mB + g];
                a[mt][1] = As[(kb + tig) * PM + mB + g + 8];
                a[mt][2] = As[(kb + tig + 4) * PM + mB + g];
                a[mt][3] = As[(kb + tig + 4) * PM + mB + g + 8];
            }
#pragma unroll
            for (int nt = 0; nt < 4; nt++) {
                int nB = nBase0 + nt * 8;
                b[nt][0] = Bs[(kb + tig) * PN + nB + g];
                b[nt][1] = Bs[(kb + tig + 4) * PN + nB + g];
            }
#pragma unroll
            for (int mt = 0; mt < 3; mt++)
#pragma unroll
                for (int nt = 0; nt < 4; nt++)
                    mma8(acc[mt][nt], a[mt], b[nt]);
        }
        __syncthreads();
    }

#pragma unroll
    for (int mt = 0; mt < 3; mt++) {
#pragma unroll
        for (int h = 0; h < 2; h++) {
            int gm = rowBase + mBase0 + mt * 16 + g + h * 8;
            if (gm < 96) {
                float bias = g_bias[gm];
                float* dst = (gm < 48) ? (g_a + ((size_t)n * 48 + gm) * TV_)
                                       : (g_b + ((size_t)n * 48 + (gm - 48)) * TV_);
#pragma unroll
                for (int nt = 0; nt < 4; nt++) {
                    int col = col0 + nBase0 + nt * 8 + tig * 2;
                    if (col < TV_) {
                        float2 v = make_float2(acc[mt][nt][h * 2 + 0] + bias,
                                               acc[mt][nt][h * 2 + 1] + bias);
                        *(float2*)(dst + col) = v;
                    }
                }
            } else {
                unsigned* dst = g_xpu + ((size_t)n * 192 + (gm - 96)) * TV_;
#pragma unroll
                for (int nt = 0; nt < 4; nt++) {
                    int col = col0 + nBase0 + nt * 8 + tig * 2;
                    if (col < TV_) {
                        uint2 v = make_uint2(f2tf32(acc[mt][nt][h * 2 + 0]),
                                             f2tf32(acc[mt][nt][h * 2 + 1]));
                        *(uint2*)(dst + col) = v;
                    }
                }
            }
        }
    }
}

// ---------------- K2a: partial scores, 2x2 register tiling, k split 5 ways ----------------
#define K2W 28
__global__ __launch_bounds__(256) void k2a() {
    __shared__ __align__(16) float ach[64 * K2W];
    __shared__ __align__(16) float bch[64 * K2W];
    const int s = blockIdx.x, n = blockIdx.y, q = blockIdx.z;
    const int tid = threadIdx.x;
    const float* abase = g_a + ((size_t)n * 48 + s * 16) * TV_;
    const float* bbase = g_b + ((size_t)n * 48 + s * 16) * TV_;
    const int tv = tid / 13, tw = tid % 13;
    const bool act = (tid < 169);
    const int v0 = 2 * tv, w0 = 2 * tw;
    float acc00 = 0.f, acc01 = 0.f, acc10 = 0.f, acc11 = 0.f;

    for (int c = q * 15; c < q * 15 + 15; c++) {
        __syncthreads();
        for (int idx = tid; idx < 64 * 26; idx += 256) {
            int kk = idx / 26, vv = idx % 26;
            int k = c * 64 + kk;
            int i = k / 300, tt = k % 300;
            float av = 0.f, bv = 0.f;
            if (vv < 25) {
                size_t off = (size_t)i * TV_ + tt * 25 + vv;
                av = abase[off]; bv = bbase[off];
            }
            ach[kk * K2W + vv] = av;
            bch[kk * K2W + vv] = bv;
        }
        __syncthreads();
        if (act) {
#pragma unroll 8
            for (int kk = 0; kk < 64; kk++) {
                float2 a2 = *(const float2*)&ach[kk * K2W + v0];
                float2 b2 = *(const float2*)&bch[kk * K2W + w0];
                acc00 = fmaf(a2.x, b2.x, acc00);
                acc01 = fmaf(a2.x, b2.y, acc01);
                acc10 = fmaf(a2.y, b2.x, acc10);
                acc11 = fmaf(a2.y, b2.y, acc11);
            }
        }
    }
    if (act) {
        float* dst = g_psc + ((size_t)(s * 64 + n) * 5 + q) * 676;
        dst[v0 * 26 + w0]           = acc00;
        dst[v0 * 26 + w0 + 1]       = acc01;
        dst[(v0 + 1) * 26 + w0]     = acc10;
        dst[(v0 + 1) * 26 + w0 + 1] = acc11;
    }
}

// ---------------- K2b: combine partials + softmax + adapt (validated tail) ----------------
__global__ __launch_bounds__(640) void k2b(const float* __restrict__ Aad,
                                           const float* __restrict__ Wad) {
    __shared__ float ssc[25][26];
    __shared__ float smax[25];
    __shared__ float ssum[25];
    const int s = blockIdx.x, n = blockIdx.y;
    const int tid = threadIdx.x;
    const int v = tid / 25, w = tid % 25;
    const float* base = g_psc + (size_t)(s * 64 + n) * 5 * 676;

    if (tid < 625) {
        float sum = base[v * 26 + w];
        sum += base[676 + v * 26 + w];
        sum += base[2 * 676 + v * 26 + w];
        sum += base[3 * 676 + v * 26 + w];
        sum += base[4 * 676 + v * 26 + w];
        ssc[v][w] = sum * (1.0f / (float)KIT_);
    }
    __syncthreads();
    if (tid < 25) {
        float m = -1e30f;
        for (int vv = 0; vv < 25; vv++) m = fmaxf(m, ssc[vv][tid]);
        smax[tid] = m;
    }
    __syncthreads();
    if (tid < 625) ssc[v][w] = expf(ssc[v][w] - smax[w]);
    __syncthreads();
    if (tid < 25) {
        float sum = 0.0f;
        for (int vv = 0; vv < 25; vv++) sum += ssc[vv][tid];
        ssum[tid] = sum;
    }
    __syncthreads();
    if (tid < 625) {
        int aw = (s * 25 + v) * 25 + w;
        g_adapt[((n * 3 + s) * 25 + v) * 25 + w] = Aad[aw] + Wad[aw] + ssc[v][w] / ssum[w];
    }
}

// ---------------- K4: tf32 MMA y = sum_s xp_s @ adapt_s + bd, fused BN partials ----------------
#define XP 36
__global__ __launch_bounds__(256) void k4_mma() {
    __shared__ __align__(16) unsigned xs[256 * XP];
    __shared__ __align__(16) unsigned ads[32 * 40];
    __shared__ float rb[256 * 4];
    const int bi = blockIdx.x;
    const int n = bi / 75;
    const int local0 = (bi % 75) * 256;
    const int tid = threadIdx.x, warp = tid >> 5, lane = tid & 31;
    const int g = lane >> 2, tig = lane & 3;
    const int mB0 = warp * 32;

    float acc[2][4][4];
#pragma unroll
    for (int mt = 0; mt < 2; mt++)
#pragma unroll
        for (int nt = 0; nt < 4; nt++)
#pragma unroll
            for (int q = 0; q < 4; q++) acc[mt][nt][q] = 0.0f;

#pragma unroll
    for (int cpd = 25; cpd < XP; cpd++) xs[tid * XP + cpd] = 0u;

    const float* adg = g_adapt + n * (S_ * V_ * V_);
    const int r0 = tid / 25, v0 = tid % 25;

    for (int s = 0; s < 3; s++) {
        __syncthreads();
        for (int i = tid; i < 1280; i += 256) {
            int v = i / 40, w = i % 40;
            float val = (v < 25 && w < 25) ? adg[(s * 25 + v) * 25 + w] : 0.0f;
            ads[i] = f2tf32(val);
        }
        // pure uint copy of xp tile (pre-converted tf32 bits), incremental indexing
        const unsigned* src = g_xpu + (size_t)n * 1440000 + (size_t)s * 480000 + (size_t)local0 * 25;
        {
            int i = tid;
            int v = v0;
            int d = r0 * XP + v0;
#pragma unroll
            for (int it = 0; it < 25; it++) {
                xs[d] = src[i];
                i += 256;
                v += 6; d += 10 * XP + 6;
                if (v >= 25) { v -= 25; d += XP - 25; }
            }
        }
        __syncthreads();
#pragma unroll
        for (int ks = 0; ks < 4; ks++) {
            const int kb = ks * 8;
            unsigned af[2][4], bf[4][2];
#pragma unroll
            for (int mt = 0; mt < 2; mt++) {
                int mB = mB0 + mt * 16;
                af[mt][0] = xs[(mB + g) * XP + kb + tig];
                af[mt][1] = xs[(mB + g + 8) * XP + kb + tig];
                af[mt][2] = xs[(mB + g) * XP + kb + tig + 4];
                af[mt][3] = xs[(mB + g + 8) * XP + kb + tig + 4];
            }
#pragma unroll
            for (int nt = 0; nt < 4; nt++) {
                bf[nt][0] = ads[(kb + tig) * 40 + nt * 8 + g];
                bf[nt][1] = ads[(kb + tig + 4) * 40 + nt * 8 + g];
            }
#pragma unroll
            for (int mt = 0; mt < 2; mt++)
#pragma unroll
                for (int nt = 0; nt < 4; nt++)
                    mma8(acc[mt][nt], af[mt], bf[nt]);
        }
    }
    __syncthreads();

    float* ys = (float*)xs;
#pragma unroll
    for (int mt = 0; mt < 2; mt++) {
#pragma unroll
        for (int h = 0; h < 2; h++) {
            int row = mB0 + mt * 16 + g + h * 8;
            float bias = g_bdsum[(local0 + row) / 300];
#pragma unroll
            for (int nt = 0; nt < 4; nt++) {
#pragma unroll
                for (int e = 0; e < 2; e++) {
                    int col = nt * 8 + tig * 2 + e;
                    if (col < 25) ys[row * 25 + col] = acc[mt][nt][h * 2 + e] + bias;
                }
            }
        }
    }
    __syncthreads();

    const int o_lo = local0 / 300;
    int split = (o_lo + 1) * 300 - local0;
    if (split > 256) split = 256;
    const int splitf = split * 25;
    float s10 = 0.f, s20 = 0.f, s11 = 0.f, s21 = 0.f;
    for (int i = tid; i < 6400; i += 256) {
        float v = ys[i];
        if (i < splitf) { s10 += v; s20 = fmaf(v, v, s20); }
        else            { s11 += v; s21 = fmaf(v, v, s21); }
    }
    rb[tid * 4 + 0] = s10; rb[tid * 4 + 1] = s20;
    rb[tid * 4 + 2] = s11; rb[tid * 4 + 3] = s21;
    __syncthreads();
    for (int off = 128; off > 0; off >>= 1) {
        if (tid < off) {
#pragma unroll
            for (int j = 0; j < 4; j++)
                rb[tid * 4 + j] += rb[(tid + off) * 4 + j];
        }
        __syncthreads();
    }
    if (tid < 4) g_pb[bi * 4 + tid] = rb[tid];

    float* dst = g_y + (size_t)n * 480000 + (size_t)local0 * 25;
    for (int i = tid * 4; i < 6400; i += 1024)
        *(float4*)&dst[i] = *(float4*)&ys[i];
}

// ---------------- K5b: reduce block partials -> scale/shift ----------------
__global__ __launch_bounds__(256) void k5b(const float* __restrict__ gamma,
                                           const float* __restrict__ beta) {
    __shared__ float r1[256], r2[256];
    const int c = blockIdx.x;
    const int tid = threadIdx.x;
    float s1 = 0.f, s2 = 0.f;
    for (int bi = tid; bi < 4800; bi += 256) {
        int lb = bi % 75;
        int l0 = lb * 256;
        int olo = l0 / 300;
        int ohi = (l0 + 255) / 300;
        const float* pb = g_pb + bi * 4;
        if (olo == c) { s1 += pb[0]; s2 += pb[1]; }
        if (ohi == c && ohi != olo) { s1 += pb[2]; s2 += pb[3]; }
    }
    r1[tid] = s1; r2[tid] = s2;
    __syncthreads();
    for (int off = 128; off > 0; off >>= 1) {
        if (tid < off) { r1[tid] += r1[tid + off]; r2[tid] += r2[tid + off]; }
        __syncthreads();
    }
    if (tid == 0) {
        double mean = (double)r1[0] / NTV_;
        double var = (double)r2[0] / NTV_ - mean * mean;
        float sc = gamma[c] * rsqrtf((float)var + 1e-5f);
        g_scale[c] = sc;
        g_shift[c] = beta[c] - (float)mean * sc;
    }
}

// ---------------- K6: BN apply + residual + relu ----------------
__global__ __launch_bounds__(256) void k6(const float* __restrict__ x, float* __restrict__ out) {
    size_t i = ((size_t)blockIdx.x * 256 + threadIdx.x) * 4;
    if (i >= (size_t)N_ * C_ * TV_) return;
    int c = (int)((i / TV_) & 63);
    float sc = g_scale[c], sh = g_shift[c];
    float4 yv = *(const float4*)&g_y[i];
    float4 xv = *(const float4*)&x[i];
    float4 o;
    o.x = fmaxf(fmaf(yv.x, sc, sh) + xv.x, 0.f);
    o.y = fmaxf(fmaf(yv.y, sc, sh) + xv.y, 0.f);
    o.z = fmaxf(fmaf(yv.z, sc, sh) + xv.z, 0.f);
    o.w = fmaxf(fmaf(yv.w, sc, sh) + xv.w, 0.f);
    *(float4*)&out[i] = o;
}

// ---------------- launch ----------------
extern "C" void kernel_launch(void* const* d_in, const int* in_sizes, int n_in,
                              void* d_out, int out_size) {
    const float* x     = (const float*)d_in[0];
    const float* Aad   = (const float*)d_in[1];
    const float* Wad   = (const float*)d_in[2];
    const float* wa    = (const float*)d_in[3];
    const float* ba    = (const float*)d_in[4];
    const float* wb    = (const float*)d_in[5];
    const float* bb    = (const float*)d_in[6];
    const float* wd    = (const float*)d_in[7];
    const float* bd    = (const float*)d_in[8];
    const float* gamma = (const float*)d_in[9];
    const float* beta  = (const float*)d_in[10];
    float* out = (float*)d_out;

    k0_pack<<<74, 256>>>(wa, ba, wb, bb, wd, bd);
    kg_tf32<<<dim3(3, 59, 64), 256>>>(x);
    k2a<<<dim3(3, 64, 5), 256>>>();
    k2b<<<dim3(3, 64), 640>>>(Aad, Wad);
    k4_mma<<<4800, 256>>>();
    k5b<<<64, 256>>>(gamma, beta);
    k6<<<30000, 256>>>(x, out);
}